// round 15
// baseline (speedup 1.0000x reference)
#include <cuda_runtime.h>
#include <cuda_fp16.h>
#include <stdint.h>

// Problem constants
#define B_BATCH 8
#define SEQ     4096
#define DIN     1024
#define DOUT    1024
#define RTOT    104

// Scratch: fp16 folded weights (16 MB) and fp16 x (64 MB)
__device__ __half g_wh[(size_t)B_BATCH * DOUT * DIN];
__device__ __half g_xh[(size_t)B_BATCH * SEQ * DIN];

__device__ __forceinline__ uint32_t smem_u32(const void* p) {
    return (uint32_t)__cvta_generic_to_shared(p);
}
__device__ __forceinline__ void cp_async16(uint32_t saddr, const void* gptr) {
    asm volatile("cp.async.cg.shared.global [%0], [%1], 16;\n" :: "r"(saddr), "l"(gptr));
}
__device__ __forceinline__ void cp_commit() {
    asm volatile("cp.async.commit_group;\n");
}
template <int N>
__device__ __forceinline__ void cp_wait() {
    asm volatile("cp.async.wait_group %0;\n" :: "n"(N));
}
__device__ __forceinline__ void ldmatrix_x4(uint32_t r[4], uint32_t addr) {
    asm volatile("ldmatrix.sync.aligned.m8n8.x4.shared.b16 {%0,%1,%2,%3}, [%4];"
                 : "=r"(r[0]), "=r"(r[1]), "=r"(r[2]), "=r"(r[3]) : "r"(addr));
}
__device__ __forceinline__ void ldmatrix_x4_trans(uint32_t r[4], uint32_t addr) {
    asm volatile("ldmatrix.sync.aligned.m8n8.x4.trans.shared.b16 {%0,%1,%2,%3}, [%4];"
                 : "=r"(r[0]), "=r"(r[1]), "=r"(r[2]), "=r"(r[3]) : "r"(addr));
}
__device__ __forceinline__ void mma_f16(float c[4], const uint32_t a[4],
                                        uint32_t b0, uint32_t b1) {
    asm volatile("mma.sync.aligned.m16n8k16.row.col.f32.f16.f16.f32 "
                 "{%0,%1,%2,%3}, {%4,%5,%6,%7}, {%8,%9}, {%0,%1,%2,%3};\n"
                 : "+f"(c[0]), "+f"(c[1]), "+f"(c[2]), "+f"(c[3])
                 : "r"(a[0]), "r"(a[1]), "r"(a[2]), "r"(a[3]), "r"(b0), "r"(b1));
}

// ---------------------------------------------------------------------------
// Per-batch conv: x[b] -> fp16 g_xh[b]. 256 fat blocks, 16 float4/thread.
// ---------------------------------------------------------------------------
#define CONV_BLOCKS_PB ((SEQ * DIN) / (4 * 4096))   // 256 per batch

__global__ __launch_bounds__(256) void conv_kernel(const float4* __restrict__ x4,
                                                   int b) {
    const int tid = threadIdx.x;
    const size_t base = (size_t)b * (SEQ * DIN / 4) + (size_t)blockIdx.x * 4096;
    #pragma unroll
    for (int p = 0; p < 2; p++) {
        float4 v[8];
        #pragma unroll
        for (int k = 0; k < 8; k++)
            v[k] = x4[base + p * 2048 + k * 256 + tid];
        #pragma unroll
        for (int k = 0; k < 8; k++) {
            size_t i = base + p * 2048 + k * 256 + tid;
            __half2* o = (__half2*)(g_xh + i * 4);
            o[0] = __floats2half2_rn(v[k].x, v[k].y);
            o[1] = __floats2half2_rn(v[k].z, v[k].w);
        }
    }
}

// ---------------------------------------------------------------------------
// Per-batch prep (64 blocks): W_eff[b] = base_w + pu_mod[b] @ pd -> g_wh[b].
// ---------------------------------------------------------------------------
#define KP 112
#define PSA 120
#define PSB 136
#define PREP_A_HALVES (128 * PSA)
#define PREP_SMEM_BYTES ((128 * PSA + KP * PSB) * 2)   // 61184
#define PREP_BLOCKS_PB (8 * 8)                          // 64 per batch

__global__ __launch_bounds__(256) void prep_kernel(
    const float* __restrict__ base_w,
    const float* __restrict__ pd_w,
    const float* __restrict__ pu_w,
    const float* __restrict__ mem_f,
    const float* __restrict__ mem_m,
    const float* __restrict__ mem_s,
    int b)
{
    extern __shared__ __half psm[];
    __half* As = psm;                  // [128][PSA]
    __half* Bs = psm + PREP_A_HALVES;  // [KP][PSB]
    __shared__ float s_fac[KP];

    const int tid = threadIdx.x;
    const int bid = blockIdx.x;
    const int d0  = (bid & 7) * 128;
    const int o0  = (bid >> 3) * 128;

    if (tid < KP) {
        float f = 0.0f;
        int r = tid;
        if (r < RTOT) {
            float memv;
            if (r < 8)       memv = mem_f[b * 8  + r];
            else if (r < 40) memv = mem_m[b * 32 + (r - 8)];
            else             memv = mem_s[b * 64 + (r - 40)];
            f = (1.0f + memv) * (1.0f / 3.0f);
        }
        s_fac[r] = f;
    }
    __syncthreads();

    // A fill: 128 rows x 28 float4-groups (groups >= 26 zero since RTOT=104)
    for (int i = tid; i < 128 * 28; i += 256) {
        int o = i / 28, g = i - o * 28;
        int r = g * 4;
        __half2 h01, h23;
        if (r < RTOT) {
            float4 v = *(const float4*)(pu_w + (size_t)(o0 + o) * RTOT + r);
            h01 = __floats2half2_rn(v.x * s_fac[r],     v.y * s_fac[r + 1]);
            h23 = __floats2half2_rn(v.z * s_fac[r + 2], v.w * s_fac[r + 3]);
        } else {
            h01 = __floats2half2_rn(0.f, 0.f);
            h23 = h01;
        }
        uint2 u; u.x = *(uint32_t*)&h01; u.y = *(uint32_t*)&h23;
        *(uint2*)&As[o * PSA + r] = u;
    }
    // B fill: KP rows x 32 float4-groups (rows >= RTOT zero)
    for (int i = tid; i < KP * 32; i += 256) {
        int r = i >> 5, g = i & 31;
        __half2 h01, h23;
        if (r < RTOT) {
            float4 v = *(const float4*)(pd_w + (size_t)r * DIN + d0 + g * 4);
            h01 = __floats2half2_rn(v.x, v.y);
            h23 = __floats2half2_rn(v.z, v.w);
        } else {
            h01 = __floats2half2_rn(0.f, 0.f);
            h23 = h01;
        }
        uint2 u; u.x = *(uint32_t*)&h01; u.y = *(uint32_t*)&h23;
        *(uint2*)&Bs[r * PSB + g * 4] = u;
    }
    __syncthreads();

    const int lane = tid & 31;
    const int wid  = tid >> 5;
    const int wm   = wid >> 2;
    const int wn   = wid & 3;

    const int mi = lane >> 3;
    const int rl = lane & 7;
    const int aRow = wm * 64 + ((mi & 1) << 3) + rl;
    const int gsel = mi >> 1;
    const int bK   = ((mi >> 1) << 3) + rl;
    const int bN   = wn * 32 + ((mi & 1) << 3);

    const uint32_t sA = smem_u32(As);
    const uint32_t sB = smem_u32(Bs);

    float acc[4][4][4];
    #pragma unroll
    for (int mf = 0; mf < 4; mf++)
        #pragma unroll
        for (int nf = 0; nf < 4; nf++)
            #pragma unroll
            for (int k = 0; k < 4; k++) acc[mf][nf][k] = 0.0f;

    #pragma unroll
    for (int ks = 0; ks < KP / 16; ks++) {
        uint32_t a[4][4], bf[2][4];
        #pragma unroll
        for (int mf = 0; mf < 4; mf++)
            ldmatrix_x4(a[mf],
                sA + (uint32_t)(((aRow + mf * 16) * PSA + ks * 16 + gsel * 8) * 2));
        #pragma unroll
        for (int nfp = 0; nfp < 2; nfp++)
            ldmatrix_x4_trans(bf[nfp],
                sB + (uint32_t)(((ks * 16 + bK) * PSB + bN + nfp * 16) * 2));
        #pragma unroll
        for (int mf = 0; mf < 4; mf++)
            #pragma unroll
            for (int nfp = 0; nfp < 2; nfp++) {
                mma_f16(acc[mf][2 * nfp + 0], a[mf], bf[nfp][0], bf[nfp][2]);
                mma_f16(acc[mf][2 * nfp + 1], a[mf], bf[nfp][1], bf[nfp][3]);
            }
    }

    const int lr = lane >> 2;
    const int lc = lane & 3;
    #pragma unroll
    for (int mf = 0; mf < 4; mf++) {
        int row = o0 + wm * 64 + mf * 16 + lr;
        #pragma unroll
        for (int nf = 0; nf < 4; nf++) {
            int col = d0 + wn * 32 + nf * 8 + lc * 2;
            const float* bwp0 = base_w + (size_t)row * DIN + col;
            const float* bwp1 = base_w + (size_t)(row + 8) * DIN + col;
            __half2 h0 = __floats2half2_rn(acc[mf][nf][0] + bwp0[0],
                                           acc[mf][nf][1] + bwp0[1]);
            __half2 h1 = __floats2half2_rn(acc[mf][nf][2] + bwp1[0],
                                           acc[mf][nf][3] + bwp1[1]);
            *(__half2*)(g_wh + ((size_t)b * DOUT + row) * DIN + col)     = h0;
            *(__half2*)(g_wh + ((size_t)b * DOUT + row + 8) * DIN + col) = h1;
        }
    }
}

// ---------------------------------------------------------------------------
// Per-batch GEMM (round-12 mainloop): out[b] = x[b] @ W_eff[b]^T + base_b.
// fp16 m16n8k16 (fp32 accum). CTA 128x128, 4 warps, warp tile 64x64,
// 3-stage cp.async, 2 CTAs/SM. Grid (8 nt, 32 mt) per batch = 256 CTAs
// (one wave at 296 slots).
// ---------------------------------------------------------------------------
#define BM 128
#define BN 128
#define BK 64
#define NKT (DIN / BK)                 // 16
#define STAGES 3
#define A_STAGE_BYTES (BM * 128)
#define B_STAGE_BYTES (BN * 128)
#define STAGE_BYTES (A_STAGE_BYTES + B_STAGE_BYTES)
#define SMEM_BYTES (STAGES * STAGE_BYTES + 1024)

__global__ __launch_bounds__(128, 2) void gemm_kernel(
    const float* __restrict__ base_b,
    float* __restrict__ out,
    int b)
{
    extern __shared__ char dsmem_raw[];
    const uint32_t dyn = (smem_u32(dsmem_raw) + 1023u) & ~1023u;

    const int tid  = threadIdx.x;
    const int lane = tid & 31;
    const int wid  = tid >> 5;        // 0..3
    const int wm   = wid >> 1;        // 0..1
    const int wn   = wid & 1;         // 0..1

    const int mt = blockIdx.y;
    const int nt = blockIdx.x;

    const __half* Ag = g_xh + ((size_t)b * SEQ  + (size_t)mt * BM) * DIN;
    const __half* Bg = g_wh + ((size_t)b * DOUT + (size_t)nt * BN) * DIN;

    const int mi    = lane >> 3;
    const int rl    = lane & 7;
    const int half8 = (mi & 1) << 3;
    const int gsel  = mi >> 1;
    const int rA    = wm * 64 + half8 + rl;
    const int rB    = wn * 64 + half8 + rl;
    const uint32_t swA = (uint32_t)(rA & 7);
    const uint32_t swB = (uint32_t)(rB & 7);

    float acc[4][8][4];
    #pragma unroll
    for (int mf = 0; mf < 4; mf++)
        #pragma unroll
        for (int nf = 0; nf < 8; nf++)
            #pragma unroll
            for (int k = 0; k < 4; k++) acc[mf][nf][k] = 0.0f;

    auto load_stage = [&](int st) {
        const int slot = st % STAGES;
        const uint32_t base = dyn + (uint32_t)slot * STAGE_BYTES;
        const int koff = st * BK;
        #pragma unroll
        for (int i = 0; i < 8; i++) {
            int c = tid + i * 128;
            int row = c >> 3, q = c & 7;
            uint32_t dst = base + (uint32_t)(row * 128) + (uint32_t)((q ^ (row & 7)) << 4);
            cp_async16(dst, Ag + (size_t)row * DIN + koff + q * 8);
        }
        #pragma unroll
        for (int i = 0; i < 8; i++) {
            int c = tid + i * 128;
            int row = c >> 3, q = c & 7;
            uint32_t dst = base + A_STAGE_BYTES + (uint32_t)(row * 128)
                         + (uint32_t)((q ^ (row & 7)) << 4);
            cp_async16(dst, Bg + (size_t)row * DIN + koff + q * 8);
        }
        cp_commit();
    };

    load_stage(0);
    load_stage(1);

    for (int kt = 0; kt < NKT; kt++) {
        cp_wait<STAGES - 2>();
        __syncthreads();

        const uint32_t At = dyn + (uint32_t)(kt % STAGES) * STAGE_BYTES;
        const uint32_t Bt = At + A_STAGE_BYTES;
        const uint32_t aBase = At + (uint32_t)(rA * 128);
        const uint32_t bBase = Bt + (uint32_t)(rB * 128);

        {
            uint32_t a[4][4], bf[4][4];
            #pragma unroll
            for (int mf = 0; mf < 4; mf++)
                ldmatrix_x4(a[mf], aBase + (uint32_t)(mf * 2048)
                                 + (((uint32_t)gsel ^ swA) << 4));
            #pragma unroll
            for (int nfp = 0; nfp < 4; nfp++)
                ldmatrix_x4(bf[nfp], bBase + (uint32_t)(nfp * 2048)
                                   + (((uint32_t)gsel ^ swB) << 4));
            #pragma unroll
            for (int mf = 0; mf < 4; mf++)
                #pragma unroll
                for (int nfp = 0; nfp < 4; nfp++) {
                    mma_f16(acc[mf][2 * nfp + 0], a[mf], bf[nfp][0], bf[nfp][2]);
                    mma_f16(acc[mf][2 * nfp + 1], a[mf], bf[nfp][1], bf[nfp][3]);
                }
        }

        if (kt + STAGES - 1 < NKT) load_stage(kt + STAGES - 1);
        else                       cp_commit();

        #pragma unroll
        for (int ks = 1; ks < 4; ks++) {
            uint32_t a[4][4], bf[4][4];
            #pragma unroll
            for (int mf = 0; mf < 4; mf++)
                ldmatrix_x4(a[mf], aBase + (uint32_t)(mf * 2048)
                                 + ((((uint32_t)(2 * ks) + gsel) ^ swA) << 4));
            #pragma unroll
            for (int nfp = 0; nfp < 4; nfp++)
                ldmatrix_x4(bf[nfp], bBase + (uint32_t)(nfp * 2048)
                                   + ((((uint32_t)(2 * ks) + gsel) ^ swB) << 4));
            #pragma unroll
            for (int mf = 0; mf < 4; mf++)
                #pragma unroll
                for (int nfp = 0; nfp < 4; nfp++) {
                    mma_f16(acc[mf][2 * nfp + 0], a[mf], bf[nfp][0], bf[nfp][2]);
                    mma_f16(acc[mf][2 * nfp + 1], a[mf], bf[nfp][1], bf[nfp][3]);
                }
        }
    }

    const int lr = lane >> 2;
    const int lc = lane & 3;
    float* Cg = out + ((size_t)b * SEQ + (size_t)mt * BM) * DOUT + (size_t)nt * BN;
    const float* bias = base_b + (size_t)nt * BN;

    #pragma unroll
    for (int mf = 0; mf < 4; mf++) {
        int row = wm * 64 + mf * 16 + lr;
        #pragma unroll
        for (int nf = 0; nf < 8; nf++) {
            int col = wn * 64 + nf * 8 + lc * 2;
            float b0 = bias[col], b1 = bias[col + 1];
            float2 r0, r1;
            r0.x = acc[mf][nf][0] + b0;
            r0.y = acc[mf][nf][1] + b1;
            r1.x = acc[mf][nf][2] + b0;
            r1.y = acc[mf][nf][3] + b1;
            *(float2*)(Cg + (size_t)row * DOUT + col)       = r0;
            *(float2*)(Cg + (size_t)(row + 8) * DOUT + col) = r1;
        }
    }
}

// ---------------------------------------------------------------------------
// Launch: per-batch pipeline over ONE side stream (round-13-proven resource
// footprint: 1 stream + events passed the allocation guard).
//   s1:        conv0,prep0,e0, conv1,prep1,e1, ...
//   stream 0:  wait(e0) gemm0, wait(e1) gemm1, ...
// gemm_0 starts after ~12us; all later pre-work hides under earlier gemms.
// ---------------------------------------------------------------------------
extern "C" void kernel_launch(void* const* d_in, const int* in_sizes, int n_in,
                              void* d_out, int out_size) {
    const float* x      = (const float*)d_in[0];
    const float* mem_f  = (const float*)d_in[1];
    const float* mem_m  = (const float*)d_in[2];
    const float* mem_s  = (const float*)d_in[3];
    const float* base_w = (const float*)d_in[4];
    const float* base_b = (const float*)d_in[5];
    const float* pd_w   = (const float*)d_in[6];
    const float* pu_w   = (const float*)d_in[7];
    // d_in[8..11]: gate network weights — mathematically dead
    // (softmax sums to 1, mean over the 3-way axis == 1/3 exactly).
    float* out = (float*)d_out;

    cudaFuncSetAttribute(prep_kernel,
                         cudaFuncAttributeMaxDynamicSharedMemorySize, PREP_SMEM_BYTES);
    cudaFuncSetAttribute(gemm_kernel,
                         cudaFuncAttributeMaxDynamicSharedMemorySize, SMEM_BYTES);

    cudaStream_t s1;
    cudaStreamCreateWithFlags(&s1, cudaStreamNonBlocking);
    cudaEvent_t ev_fork, e[B_BATCH];
    cudaEventCreateWithFlags(&ev_fork, cudaEventDisableTiming);
    cudaEventRecord(ev_fork, 0);
    cudaStreamWaitEvent(s1, ev_fork, 0);

    for (int b = 0; b < B_BATCH; b++) {
        cudaEventCreateWithFlags(&e[b], cudaEventDisableTiming);
        conv_kernel<<<CONV_BLOCKS_PB, 256, 0, s1>>>((const float4*)x, b);
        prep_kernel<<<PREP_BLOCKS_PB, 256, PREP_SMEM_BYTES, s1>>>(
            base_w, pd_w, pu_w, mem_f, mem_m, mem_s, b);
        cudaEventRecord(e[b], s1);
    }
    for (int b = 0; b < B_BATCH; b++) {
        cudaStreamWaitEvent(0, e[b], 0);
        gemm_kernel<<<dim3(DOUT / BN, SEQ / BM, 1), 128, SMEM_BYTES>>>(
            base_b, out, b);
    }

    cudaStreamDestroy(s1);
    for (int b = 0; b < B_BATCH; b++) cudaEventDestroy(e[b]);
    cudaEventDestroy(ev_fork);
}

// round 16
// speedup vs baseline: 1.0140x; 1.0140x over previous
#include <cuda_runtime.h>
#include <cuda_fp16.h>
#include <stdint.h>

// Problem constants
#define B_BATCH 8
#define SEQ     4096
#define DIN     1024
#define DOUT    1024
#define RTOT    104

// Scratch: fp16 folded weights (16 MB) and fp16 x (64 MB)
__device__ __half g_wh[(size_t)B_BATCH * DOUT * DIN];
__device__ __half g_xh[(size_t)B_BATCH * SEQ * DIN];

__device__ __forceinline__ uint32_t smem_u32(const void* p) {
    return (uint32_t)__cvta_generic_to_shared(p);
}
__device__ __forceinline__ void cp_async16(uint32_t saddr, const void* gptr) {
    asm volatile("cp.async.cg.shared.global [%0], [%1], 16;\n" :: "r"(saddr), "l"(gptr));
}
__device__ __forceinline__ void cp_commit() {
    asm volatile("cp.async.commit_group;\n");
}
template <int N>
__device__ __forceinline__ void cp_wait() {
    asm volatile("cp.async.wait_group %0;\n" :: "n"(N));
}
__device__ __forceinline__ void ldmatrix_x4(uint32_t r[4], uint32_t addr) {
    asm volatile("ldmatrix.sync.aligned.m8n8.x4.shared.b16 {%0,%1,%2,%3}, [%4];"
                 : "=r"(r[0]), "=r"(r[1]), "=r"(r[2]), "=r"(r[3]) : "r"(addr));
}
__device__ __forceinline__ void ldmatrix_x4_trans(uint32_t r[4], uint32_t addr) {
    asm volatile("ldmatrix.sync.aligned.m8n8.x4.trans.shared.b16 {%0,%1,%2,%3}, [%4];"
                 : "=r"(r[0]), "=r"(r[1]), "=r"(r[2]), "=r"(r[3]) : "r"(addr));
}
__device__ __forceinline__ void mma_f16(float c[4], const uint32_t a[4],
                                        uint32_t b0, uint32_t b1) {
    asm volatile("mma.sync.aligned.m16n8k16.row.col.f32.f16.f16.f32 "
                 "{%0,%1,%2,%3}, {%4,%5,%6,%7}, {%8,%9}, {%0,%1,%2,%3};\n"
                 : "+f"(c[0]), "+f"(c[1]), "+f"(c[2]), "+f"(c[3])
                 : "r"(a[0]), "r"(a[1]), "r"(a[2]), "r"(a[3]), "r"(b0), "r"(b1));
}

// ---------------------------------------------------------------------------
// Per-batch conv: x[b] -> fp16 g_xh[b]. 256 fat blocks, 16 float4/thread.
// ---------------------------------------------------------------------------
#define CONV_BLOCKS_PB ((SEQ * DIN) / (4 * 4096))   // 256 per batch

__global__ __launch_bounds__(256) void conv_kernel(const float4* __restrict__ x4,
                                                   int b) {
    const int tid = threadIdx.x;
    const size_t base = (size_t)b * (SEQ * DIN / 4) + (size_t)blockIdx.x * 4096;
    #pragma unroll
    for (int p = 0; p < 2; p++) {
        float4 v[8];
        #pragma unroll
        for (int k = 0; k < 8; k++)
            v[k] = x4[base + p * 2048 + k * 256 + tid];
        #pragma unroll
        for (int k = 0; k < 8; k++) {
            size_t i = base + p * 2048 + k * 256 + tid;
            __half2* o = (__half2*)(g_xh + i * 4);
            o[0] = __floats2half2_rn(v[k].x, v[k].y);
            o[1] = __floats2half2_rn(v[k].z, v[k].w);
        }
    }
}

// ---------------------------------------------------------------------------
// Monolithic prep (512 blocks, ALL batches — the efficient amortized form):
// W_eff[b] = base_w + pu_mod[b] @ pd -> g_wh (fp16), tensor-core path.
// ---------------------------------------------------------------------------
#define KP 112
#define PSA 120
#define PSB 136
#define PREP_A_HALVES (128 * PSA)
#define PREP_SMEM_BYTES ((128 * PSA + KP * PSB) * 2)   // 61184
#define PREP_BLOCKS (8 * 8 * B_BATCH)                  // 512

__global__ __launch_bounds__(256) void prep_kernel(
    const float* __restrict__ base_w,
    const float* __restrict__ pd_w,
    const float* __restrict__ pu_w,
    const float* __restrict__ mem_f,
    const float* __restrict__ mem_m,
    const float* __restrict__ mem_s)
{
    extern __shared__ __half psm[];
    __half* As = psm;                  // [128][PSA]
    __half* Bs = psm + PREP_A_HALVES;  // [KP][PSB]
    __shared__ float s_fac[KP];

    const int tid = threadIdx.x;
    const int bid = blockIdx.x;
    const int d0  = (bid & 7) * 128;
    const int o0  = ((bid >> 3) & 7) * 128;
    const int b   = bid >> 6;

    if (tid < KP) {
        float f = 0.0f;
        int r = tid;
        if (r < RTOT) {
            float memv;
            if (r < 8)       memv = mem_f[b * 8  + r];
            else if (r < 40) memv = mem_m[b * 32 + (r - 8)];
            else             memv = mem_s[b * 64 + (r - 40)];
            f = (1.0f + memv) * (1.0f / 3.0f);
        }
        s_fac[r] = f;
    }
    __syncthreads();

    // A fill: 128 rows x 28 float4-groups (groups >= 26 zero since RTOT=104)
    for (int i = tid; i < 128 * 28; i += 256) {
        int o = i / 28, g = i - o * 28;
        int r = g * 4;
        __half2 h01, h23;
        if (r < RTOT) {
            float4 v = *(const float4*)(pu_w + (size_t)(o0 + o) * RTOT + r);
            h01 = __floats2half2_rn(v.x * s_fac[r],     v.y * s_fac[r + 1]);
            h23 = __floats2half2_rn(v.z * s_fac[r + 2], v.w * s_fac[r + 3]);
        } else {
            h01 = __floats2half2_rn(0.f, 0.f);
            h23 = h01;
        }
        uint2 u; u.x = *(uint32_t*)&h01; u.y = *(uint32_t*)&h23;
        *(uint2*)&As[o * PSA + r] = u;
    }
    // B fill: KP rows x 32 float4-groups (rows >= RTOT zero)
    for (int i = tid; i < KP * 32; i += 256) {
        int r = i >> 5, g = i & 31;
        __half2 h01, h23;
        if (r < RTOT) {
            float4 v = *(const float4*)(pd_w + (size_t)r * DIN + d0 + g * 4);
            h01 = __floats2half2_rn(v.x, v.y);
            h23 = __floats2half2_rn(v.z, v.w);
        } else {
            h01 = __floats2half2_rn(0.f, 0.f);
            h23 = h01;
        }
        uint2 u; u.x = *(uint32_t*)&h01; u.y = *(uint32_t*)&h23;
        *(uint2*)&Bs[r * PSB + g * 4] = u;
    }
    __syncthreads();

    const int lane = tid & 31;
    const int wid  = tid >> 5;
    const int wm   = wid >> 2;
    const int wn   = wid & 3;

    const int mi = lane >> 3;
    const int rl = lane & 7;
    const int aRow = wm * 64 + ((mi & 1) << 3) + rl;
    const int gsel = mi >> 1;
    const int bK   = ((mi >> 1) << 3) + rl;
    const int bN   = wn * 32 + ((mi & 1) << 3);

    const uint32_t sA = smem_u32(As);
    const uint32_t sB = smem_u32(Bs);

    float acc[4][4][4];
    #pragma unroll
    for (int mf = 0; mf < 4; mf++)
        #pragma unroll
        for (int nf = 0; nf < 4; nf++)
            #pragma unroll
            for (int k = 0; k < 4; k++) acc[mf][nf][k] = 0.0f;

    #pragma unroll
    for (int ks = 0; ks < KP / 16; ks++) {
        uint32_t a[4][4], bf[2][4];
        #pragma unroll
        for (int mf = 0; mf < 4; mf++)
            ldmatrix_x4(a[mf],
                sA + (uint32_t)(((aRow + mf * 16) * PSA + ks * 16 + gsel * 8) * 2));
        #pragma unroll
        for (int nfp = 0; nfp < 2; nfp++)
            ldmatrix_x4_trans(bf[nfp],
                sB + (uint32_t)(((ks * 16 + bK) * PSB + bN + nfp * 16) * 2));
        #pragma unroll
        for (int mf = 0; mf < 4; mf++)
            #pragma unroll
            for (int nfp = 0; nfp < 2; nfp++) {
                mma_f16(acc[mf][2 * nfp + 0], a[mf], bf[nfp][0], bf[nfp][2]);
                mma_f16(acc[mf][2 * nfp + 1], a[mf], bf[nfp][1], bf[nfp][3]);
            }
    }

    const int lr = lane >> 2;
    const int lc = lane & 3;
    #pragma unroll
    for (int mf = 0; mf < 4; mf++) {
        int row = o0 + wm * 64 + mf * 16 + lr;
        #pragma unroll
        for (int nf = 0; nf < 4; nf++) {
            int col = d0 + wn * 32 + nf * 8 + lc * 2;
            const float* bwp0 = base_w + (size_t)row * DIN + col;
            const float* bwp1 = base_w + (size_t)(row + 8) * DIN + col;
            __half2 h0 = __floats2half2_rn(acc[mf][nf][0] + bwp0[0],
                                           acc[mf][nf][1] + bwp0[1]);
            __half2 h1 = __floats2half2_rn(acc[mf][nf][2] + bwp1[0],
                                           acc[mf][nf][3] + bwp1[1]);
            *(__half2*)(g_wh + ((size_t)b * DOUT + row) * DIN + col)     = h0;
            *(__half2*)(g_wh + ((size_t)b * DOUT + row + 8) * DIN + col) = h1;
        }
    }
}

// ---------------------------------------------------------------------------
// Per-batch GEMM (round-12 mainloop): out[b] = x[b] @ W_eff[b]^T + base_b.
// fp16 m16n8k16 (fp32 accum). CTA 128x128, 4 warps, warp tile 64x64,
// 3-stage cp.async, 2 CTAs/SM. Grid (8 nt, 32 mt) = 256 CTAs (one wave).
// ---------------------------------------------------------------------------
#define BM 128
#define BN 128
#define BK 64
#define NKT (DIN / BK)                 // 16
#define STAGES 3
#define A_STAGE_BYTES (BM * 128)
#define B_STAGE_BYTES (BN * 128)
#define STAGE_BYTES (A_STAGE_BYTES + B_STAGE_BYTES)
#define SMEM_BYTES (STAGES * STAGE_BYTES + 1024)

__global__ __launch_bounds__(128, 2) void gemm_kernel(
    const float* __restrict__ base_b,
    float* __restrict__ out,
    int b)
{
    extern __shared__ char dsmem_raw[];
    const uint32_t dyn = (smem_u32(dsmem_raw) + 1023u) & ~1023u;

    const int tid  = threadIdx.x;
    const int lane = tid & 31;
    const int wid  = tid >> 5;        // 0..3
    const int wm   = wid >> 1;        // 0..1
    const int wn   = wid & 1;         // 0..1

    const int mt = blockIdx.y;
    const int nt = blockIdx.x;

    const __half* Ag = g_xh + ((size_t)b * SEQ  + (size_t)mt * BM) * DIN;
    const __half* Bg = g_wh + ((size_t)b * DOUT + (size_t)nt * BN) * DIN;

    const int mi    = lane >> 3;
    const int rl    = lane & 7;
    const int half8 = (mi & 1) << 3;
    const int gsel  = mi >> 1;
    const int rA    = wm * 64 + half8 + rl;
    const int rB    = wn * 64 + half8 + rl;
    const uint32_t swA = (uint32_t)(rA & 7);
    const uint32_t swB = (uint32_t)(rB & 7);

    float acc[4][8][4];
    #pragma unroll
    for (int mf = 0; mf < 4; mf++)
        #pragma unroll
        for (int nf = 0; nf < 8; nf++)
            #pragma unroll
            for (int k = 0; k < 4; k++) acc[mf][nf][k] = 0.0f;

    auto load_stage = [&](int st) {
        const int slot = st % STAGES;
        const uint32_t base = dyn + (uint32_t)slot * STAGE_BYTES;
        const int koff = st * BK;
        #pragma unroll
        for (int i = 0; i < 8; i++) {
            int c = tid + i * 128;
            int row = c >> 3, q = c & 7;
            uint32_t dst = base + (uint32_t)(row * 128) + (uint32_t)((q ^ (row & 7)) << 4);
            cp_async16(dst, Ag + (size_t)row * DIN + koff + q * 8);
        }
        #pragma unroll
        for (int i = 0; i < 8; i++) {
            int c = tid + i * 128;
            int row = c >> 3, q = c & 7;
            uint32_t dst = base + A_STAGE_BYTES + (uint32_t)(row * 128)
                         + (uint32_t)((q ^ (row & 7)) << 4);
            cp_async16(dst, Bg + (size_t)row * DIN + koff + q * 8);
        }
        cp_commit();
    };

    load_stage(0);
    load_stage(1);

    for (int kt = 0; kt < NKT; kt++) {
        cp_wait<STAGES - 2>();
        __syncthreads();

        const uint32_t At = dyn + (uint32_t)(kt % STAGES) * STAGE_BYTES;
        const uint32_t Bt = At + A_STAGE_BYTES;
        const uint32_t aBase = At + (uint32_t)(rA * 128);
        const uint32_t bBase = Bt + (uint32_t)(rB * 128);

        {
            uint32_t a[4][4], bf[4][4];
            #pragma unroll
            for (int mf = 0; mf < 4; mf++)
                ldmatrix_x4(a[mf], aBase + (uint32_t)(mf * 2048)
                                 + (((uint32_t)gsel ^ swA) << 4));
            #pragma unroll
            for (int nfp = 0; nfp < 4; nfp++)
                ldmatrix_x4(bf[nfp], bBase + (uint32_t)(nfp * 2048)
                                   + (((uint32_t)gsel ^ swB) << 4));
            #pragma unroll
            for (int mf = 0; mf < 4; mf++)
                #pragma unroll
                for (int nfp = 0; nfp < 4; nfp++) {
                    mma_f16(acc[mf][2 * nfp + 0], a[mf], bf[nfp][0], bf[nfp][2]);
                    mma_f16(acc[mf][2 * nfp + 1], a[mf], bf[nfp][1], bf[nfp][3]);
                }
        }

        if (kt + STAGES - 1 < NKT) load_stage(kt + STAGES - 1);
        else                       cp_commit();

        #pragma unroll
        for (int ks = 1; ks < 4; ks++) {
            uint32_t a[4][4], bf[4][4];
            #pragma unroll
            for (int mf = 0; mf < 4; mf++)
                ldmatrix_x4(a[mf], aBase + (uint32_t)(mf * 2048)
                                 + ((((uint32_t)(2 * ks) + gsel) ^ swA) << 4));
            #pragma unroll
            for (int nfp = 0; nfp < 4; nfp++)
                ldmatrix_x4(bf[nfp], bBase + (uint32_t)(nfp * 2048)
                                   + ((((uint32_t)(2 * ks) + gsel) ^ swB) << 4));
            #pragma unroll
            for (int mf = 0; mf < 4; mf++)
                #pragma unroll
                for (int nfp = 0; nfp < 4; nfp++) {
                    mma_f16(acc[mf][2 * nfp + 0], a[mf], bf[nfp][0], bf[nfp][2]);
                    mma_f16(acc[mf][2 * nfp + 1], a[mf], bf[nfp][1], bf[nfp][3]);
                }
        }
    }

    const int lr = lane >> 2;
    const int lc = lane & 3;
    float* Cg = out + ((size_t)b * SEQ + (size_t)mt * BM) * DOUT + (size_t)nt * BN;
    const float* bias = base_b + (size_t)nt * BN;

    #pragma unroll
    for (int mf = 0; mf < 4; mf++) {
        int row = wm * 64 + mf * 16 + lr;
        #pragma unroll
        for (int nf = 0; nf < 8; nf++) {
            int col = wn * 64 + nf * 8 + lc * 2;
            float b0 = bias[col], b1 = bias[col + 1];
            float2 r0, r1;
            r0.x = acc[mf][nf][0] + b0;
            r0.y = acc[mf][nf][1] + b1;
            r1.x = acc[mf][nf][2] + b0;
            r1.y = acc[mf][nf][3] + b1;
            *(float2*)(Cg + (size_t)row * DOUT + col)       = r0;
            *(float2*)(Cg + (size_t)(row + 8) * DOUT + col) = r1;
        }
    }
}

// ---------------------------------------------------------------------------
// Launch: monolithic prep + per-batch conv/gemm pipeline on ONE side stream.
//   s1:        conv_0, prep_all, e0, conv_1, e1, ..., conv_7, e7
//   stream 0:  wait(e_b) -> gemm_b
// gemm_0 starts at ~43us (conv_0 + prep_all); convs 1-7 hide under gemms.
// Resource footprint (1 stream + 9 events) identical to round 15, which
// passed the allocation guard.
// ---------------------------------------------------------------------------
extern "C" void kernel_launch(void* const* d_in, const int* in_sizes, int n_in,
                              void* d_out, int out_size) {
    const float* x      = (const float*)d_in[0];
    const float* mem_f  = (const float*)d_in[1];
    const float* mem_m  = (const float*)d_in[2];
    const float* mem_s  = (const float*)d_in[3];
    const float* base_w = (const float*)d_in[4];
    const float* base_b = (const float*)d_in[5];
    const float* pd_w   = (const float*)d_in[6];
    const float* pu_w   = (const float*)d_in[7];
    // d_in[8..11]: gate network weights — mathematically dead
    // (softmax sums to 1, mean over the 3-way axis == 1/3 exactly).
    float* out = (float*)d_out;

    cudaFuncSetAttribute(prep_kernel,
                         cudaFuncAttributeMaxDynamicSharedMemorySize, PREP_SMEM_BYTES);
    cudaFuncSetAttribute(gemm_kernel,
                         cudaFuncAttributeMaxDynamicSharedMemorySize, SMEM_BYTES);

    cudaStream_t s1;
    cudaStreamCreateWithFlags(&s1, cudaStreamNonBlocking);
    cudaEvent_t ev_fork, e[B_BATCH];
    cudaEventCreateWithFlags(&ev_fork, cudaEventDisableTiming);
    cudaEventRecord(ev_fork, 0);
    cudaStreamWaitEvent(s1, ev_fork, 0);

    // Side stream: conv_0 first (gemm_0's x), then the whole prep, then the
    // remaining convs. Each e_b certifies conv_b AND (for b>=0) prep_all.
    conv_kernel<<<CONV_BLOCKS_PB, 256, 0, s1>>>((const float4*)x, 0);
    prep_kernel<<<PREP_BLOCKS, 256, PREP_SMEM_BYTES, s1>>>(
        base_w, pd_w, pu_w, mem_f, mem_m, mem_s);
    cudaEventCreateWithFlags(&e[0], cudaEventDisableTiming);
    cudaEventRecord(e[0], s1);
    for (int b = 1; b < B_BATCH; b++) {
        cudaEventCreateWithFlags(&e[b], cudaEventDisableTiming);
        conv_kernel<<<CONV_BLOCKS_PB, 256, 0, s1>>>((const float4*)x, b);
        cudaEventRecord(e[b], s1);
    }

    for (int b = 0; b < B_BATCH; b++) {
        cudaStreamWaitEvent(0, e[b], 0);
        gemm_kernel<<<dim3(DOUT / BN, SEQ / BM, 1), 128, SMEM_BYTES>>>(
            base_b, out, b);
    }

    cudaStreamDestroy(s1);
    for (int b = 0; b < B_BATCH; b++) cudaEventDestroy(e[b]);
    cudaEventDestroy(ev_fork);
}

// round 17
// speedup vs baseline: 1.1631x; 1.1470x over previous
#include <cuda_runtime.h>
#include <cuda_fp16.h>
#include <stdint.h>

// Problem constants
#define B_BATCH 8
#define SEQ     4096
#define DIN     1024
#define DOUT    1024
#define RTOT    104

// Scratch: fp16 folded weights (16 MB) and fp16 x (64 MB)
__device__ __half g_wh[(size_t)B_BATCH * DOUT * DIN];
__device__ __half g_xh[(size_t)B_BATCH * SEQ * DIN];

__device__ __forceinline__ uint32_t smem_u32(const void* p) {
    return (uint32_t)__cvta_generic_to_shared(p);
}
__device__ __forceinline__ void cp_async16(uint32_t saddr, const void* gptr) {
    asm volatile("cp.async.cg.shared.global [%0], [%1], 16;\n" :: "r"(saddr), "l"(gptr));
}
__device__ __forceinline__ void cp_commit() {
    asm volatile("cp.async.commit_group;\n");
}
template <int N>
__device__ __forceinline__ void cp_wait() {
    asm volatile("cp.async.wait_group %0;\n" :: "n"(N));
}
__device__ __forceinline__ void ldmatrix_x4(uint32_t r[4], uint32_t addr) {
    asm volatile("ldmatrix.sync.aligned.m8n8.x4.shared.b16 {%0,%1,%2,%3}, [%4];"
                 : "=r"(r[0]), "=r"(r[1]), "=r"(r[2]), "=r"(r[3]) : "r"(addr));
}
__device__ __forceinline__ void ldmatrix_x4_trans(uint32_t r[4], uint32_t addr) {
    asm volatile("ldmatrix.sync.aligned.m8n8.x4.trans.shared.b16 {%0,%1,%2,%3}, [%4];"
                 : "=r"(r[0]), "=r"(r[1]), "=r"(r[2]), "=r"(r[3]) : "r"(addr));
}
__device__ __forceinline__ void mma_f16(float c[4], const uint32_t a[4],
                                        uint32_t b0, uint32_t b1) {
    asm volatile("mma.sync.aligned.m16n8k16.row.col.f32.f16.f16.f32 "
                 "{%0,%1,%2,%3}, {%4,%5,%6,%7}, {%8,%9}, {%0,%1,%2,%3};\n"
                 : "+f"(c[0]), "+f"(c[1]), "+f"(c[2]), "+f"(c[3])
                 : "r"(a[0]), "r"(a[1]), "r"(a[2]), "r"(a[3]), "r"(b0), "r"(b1));
}

// ---------------------------------------------------------------------------
// Fused pre-pass (round-11 exact form, best measured 65.7us): CONV blocks
// first (saturate DRAM from t=0), PREP blocks after.
// Conv: 2048 fat blocks, 16 float4/thread (2 x unroll-8, MLP=8).
// Prep: 512 blocks, one (b, o-tile, d-tile) each, tensor-core path.
// ---------------------------------------------------------------------------
#define KP 112
#define PSA 120
#define PSB 136
#define PREP_A_HALVES (128 * PSA)
#define PREP_SMEM_BYTES ((128 * PSA + KP * PSB) * 2)   // 61184
#define CONV_BLOCKS ((B_BATCH * SEQ * DIN) / (4 * 4096))  // 2048
#define PREP_BLOCKS (8 * 8 * B_BATCH)                     // 512

__global__ __launch_bounds__(256) void fused_pre_kernel(
    const float4* __restrict__ x4,
    const float* __restrict__ base_w,
    const float* __restrict__ pd_w,
    const float* __restrict__ pu_w,
    const float* __restrict__ mem_f,
    const float* __restrict__ mem_m,
    const float* __restrict__ mem_s)
{
    const int tid = threadIdx.x;

    if (blockIdx.x < CONV_BLOCKS) {
        // ---- conv branch: x -> fp16, 16 float4 per thread (2 passes of 8) ----
        const size_t base = (size_t)blockIdx.x * 4096;
        #pragma unroll
        for (int p = 0; p < 2; p++) {
            float4 v[8];
            #pragma unroll
            for (int k = 0; k < 8; k++)
                v[k] = x4[base + p * 2048 + k * 256 + tid];
            #pragma unroll
            for (int k = 0; k < 8; k++) {
                size_t i = base + p * 2048 + k * 256 + tid;
                __half2* o = (__half2*)(g_xh + i * 4);
                o[0] = __floats2half2_rn(v[k].x, v[k].y);
                o[1] = __floats2half2_rn(v[k].z, v[k].w);
            }
        }
        return;
    }

    // ---- prep branch: W_eff[b] = base_w + pu_mod[b] @ pd -> g_wh (fp16) ----
    extern __shared__ __half psm[];
    __half* As = psm;                  // [128][PSA]
    __half* Bs = psm + PREP_A_HALVES;  // [KP][PSB]
    __shared__ float s_fac[KP];

    const int bid = blockIdx.x - CONV_BLOCKS;
    const int d0  = (bid & 7) * 128;
    const int o0  = ((bid >> 3) & 7) * 128;
    const int b   = bid >> 6;

    if (tid < KP) {
        float f = 0.0f;
        int r = tid;
        if (r < RTOT) {
            float memv;
            if (r < 8)       memv = mem_f[b * 8  + r];
            else if (r < 40) memv = mem_m[b * 32 + (r - 8)];
            else             memv = mem_s[b * 64 + (r - 40)];
            f = (1.0f + memv) * (1.0f / 3.0f);
        }
        s_fac[r] = f;
    }
    __syncthreads();

    // A fill: 128 rows x 28 float4-groups (groups >= 26 zero since RTOT=104)
    for (int i = tid; i < 128 * 28; i += 256) {
        int o = i / 28, g = i - o * 28;
        int r = g * 4;
        __half2 h01, h23;
        if (r < RTOT) {
            float4 v = *(const float4*)(pu_w + (size_t)(o0 + o) * RTOT + r);
            h01 = __floats2half2_rn(v.x * s_fac[r],     v.y * s_fac[r + 1]);
            h23 = __floats2half2_rn(v.z * s_fac[r + 2], v.w * s_fac[r + 3]);
        } else {
            h01 = __floats2half2_rn(0.f, 0.f);
            h23 = h01;
        }
        uint2 u; u.x = *(uint32_t*)&h01; u.y = *(uint32_t*)&h23;
        *(uint2*)&As[o * PSA + r] = u;
    }
    // B fill: KP rows x 32 float4-groups (rows >= RTOT zero)
    for (int i = tid; i < KP * 32; i += 256) {
        int r = i >> 5, g = i & 31;
        __half2 h01, h23;
        if (r < RTOT) {
            float4 v = *(const float4*)(pd_w + (size_t)r * DIN + d0 + g * 4);
            h01 = __floats2half2_rn(v.x, v.y);
            h23 = __floats2half2_rn(v.z, v.w);
        } else {
            h01 = __floats2half2_rn(0.f, 0.f);
            h23 = h01;
        }
        uint2 u; u.x = *(uint32_t*)&h01; u.y = *(uint32_t*)&h23;
        *(uint2*)&Bs[r * PSB + g * 4] = u;
    }
    __syncthreads();

    const int lane = tid & 31;
    const int wid  = tid >> 5;
    const int wm   = wid >> 2;
    const int wn   = wid & 3;

    const int mi = lane >> 3;
    const int rl = lane & 7;
    const int aRow = wm * 64 + ((mi & 1) << 3) + rl;
    const int gsel = mi >> 1;
    const int bK   = ((mi >> 1) << 3) + rl;
    const int bN   = wn * 32 + ((mi & 1) << 3);

    const uint32_t sA = smem_u32(As);
    const uint32_t sB = smem_u32(Bs);

    float acc[4][4][4];
    #pragma unroll
    for (int mf = 0; mf < 4; mf++)
        #pragma unroll
        for (int nf = 0; nf < 4; nf++)
            #pragma unroll
            for (int k = 0; k < 4; k++) acc[mf][nf][k] = 0.0f;

    #pragma unroll
    for (int ks = 0; ks < KP / 16; ks++) {
        uint32_t a[4][4], bf[2][4];
        #pragma unroll
        for (int mf = 0; mf < 4; mf++)
            ldmatrix_x4(a[mf],
                sA + (uint32_t)(((aRow + mf * 16) * PSA + ks * 16 + gsel * 8) * 2));
        #pragma unroll
        for (int nfp = 0; nfp < 2; nfp++)
            ldmatrix_x4_trans(bf[nfp],
                sB + (uint32_t)(((ks * 16 + bK) * PSB + bN + nfp * 16) * 2));
        #pragma unroll
        for (int mf = 0; mf < 4; mf++)
            #pragma unroll
            for (int nfp = 0; nfp < 2; nfp++) {
                mma_f16(acc[mf][2 * nfp + 0], a[mf], bf[nfp][0], bf[nfp][2]);
                mma_f16(acc[mf][2 * nfp + 1], a[mf], bf[nfp][1], bf[nfp][3]);
            }
    }

    const int lr = lane >> 2;
    const int lc = lane & 3;
    #pragma unroll
    for (int mf = 0; mf < 4; mf++) {
        int row = o0 + wm * 64 + mf * 16 + lr;
        #pragma unroll
        for (int nf = 0; nf < 4; nf++) {
            int col = d0 + wn * 32 + nf * 8 + lc * 2;
            const float* bwp0 = base_w + (size_t)row * DIN + col;
            const float* bwp1 = base_w + (size_t)(row + 8) * DIN + col;
            __half2 h0 = __floats2half2_rn(acc[mf][nf][0] + bwp0[0],
                                           acc[mf][nf][1] + bwp0[1]);
            __half2 h1 = __floats2half2_rn(acc[mf][nf][2] + bwp1[0],
                                           acc[mf][nf][3] + bwp1[1]);
            *(__half2*)(g_wh + ((size_t)b * DOUT + row) * DIN + col)     = h0;
            *(__half2*)(g_wh + ((size_t)b * DOUT + row + 8) * DIN + col) = h1;
        }
    }
}

// ---------------------------------------------------------------------------
// Main GEMM (round-12 exact form, best measured 196.0us):
// out[b] = x[b] @ W_eff[b]^T + base_b.
// fp16 m16n8k16 (fp32 accum). CTA 128x128 with FOUR warps (128 threads),
// warp grid 2x2, warp tile 64x64 (8 LDSM : 32 MMA per ks). 3-stage cp.async,
// 2 CTAs/SM; ks0 issued before next-stage loads. Monolithic grid (8,32,8).
// ---------------------------------------------------------------------------
#define BM 128
#define BN 128
#define BK 64
#define NKT (DIN / BK)                 // 16
#define STAGES 3
#define A_STAGE_BYTES (BM * 128)       // 16 KB
#define B_STAGE_BYTES (BN * 128)       // 16 KB
#define STAGE_BYTES (A_STAGE_BYTES + B_STAGE_BYTES)   // 32 KB
#define SMEM_BYTES (STAGES * STAGE_BYTES + 1024)

__global__ __launch_bounds__(128, 2) void gemm_kernel(
    const float* __restrict__ base_b,
    float* __restrict__ out)
{
    extern __shared__ char dsmem_raw[];
    const uint32_t dyn = (smem_u32(dsmem_raw) + 1023u) & ~1023u;

    const int tid  = threadIdx.x;
    const int lane = tid & 31;
    const int wid  = tid >> 5;        // 0..3
    const int wm   = wid >> 1;        // 0..1: 64-row M band
    const int wn   = wid & 1;         // 0..1: 64-col N band

    const int b  = blockIdx.z;
    const int mt = blockIdx.y;
    const int nt = blockIdx.x;

    const __half* Ag = g_xh + ((size_t)b * SEQ  + (size_t)mt * BM) * DIN;
    const __half* Bg = g_wh + ((size_t)b * DOUT + (size_t)nt * BN) * DIN;

    const int mi    = lane >> 3;
    const int rl    = lane & 7;
    const int half8 = (mi & 1) << 3;
    const int gsel  = mi >> 1;
    const int rA    = wm * 64 + half8 + rl;
    const int rB    = wn * 64 + half8 + rl;
    const uint32_t swA = (uint32_t)(rA & 7);
    const uint32_t swB = (uint32_t)(rB & 7);

    float acc[4][8][4];
    #pragma unroll
    for (int mf = 0; mf < 4; mf++)
        #pragma unroll
        for (int nf = 0; nf < 8; nf++)
            #pragma unroll
            for (int k = 0; k < 4; k++) acc[mf][nf][k] = 0.0f;

    auto load_stage = [&](int st) {
        const int slot = st % STAGES;
        const uint32_t base = dyn + (uint32_t)slot * STAGE_BYTES;
        const int koff = st * BK;
        #pragma unroll
        for (int i = 0; i < 8; i++) {       // A: 1024 chunks / 128 thr
            int c = tid + i * 128;
            int row = c >> 3, q = c & 7;
            uint32_t dst = base + (uint32_t)(row * 128) + (uint32_t)((q ^ (row & 7)) << 4);
            cp_async16(dst, Ag + (size_t)row * DIN + koff + q * 8);
        }
        #pragma unroll
        for (int i = 0; i < 8; i++) {       // B: 1024 chunks / 128 thr
            int c = tid + i * 128;
            int row = c >> 3, q = c & 7;
            uint32_t dst = base + A_STAGE_BYTES + (uint32_t)(row * 128)
                         + (uint32_t)((q ^ (row & 7)) << 4);
            cp_async16(dst, Bg + (size_t)row * DIN + koff + q * 8);
        }
        cp_commit();
    };

    load_stage(0);
    load_stage(1);

    for (int kt = 0; kt < NKT; kt++) {
        cp_wait<STAGES - 2>();
        __syncthreads();

        const uint32_t At = dyn + (uint32_t)(kt % STAGES) * STAGE_BYTES;
        const uint32_t Bt = At + A_STAGE_BYTES;
        const uint32_t aBase = At + (uint32_t)(rA * 128);
        const uint32_t bBase = Bt + (uint32_t)(rB * 128);

        // ks = 0 first: restart the tensor pipe immediately after the barrier
        {
            uint32_t a[4][4], bf[4][4];
            #pragma unroll
            for (int mf = 0; mf < 4; mf++)
                ldmatrix_x4(a[mf], aBase + (uint32_t)(mf * 2048)
                                 + (((uint32_t)gsel ^ swA) << 4));
            #pragma unroll
            for (int nfp = 0; nfp < 4; nfp++)
                ldmatrix_x4(bf[nfp], bBase + (uint32_t)(nfp * 2048)
                                   + (((uint32_t)gsel ^ swB) << 4));
            #pragma unroll
            for (int mf = 0; mf < 4; mf++)
                #pragma unroll
                for (int nfp = 0; nfp < 4; nfp++) {
                    mma_f16(acc[mf][2 * nfp + 0], a[mf], bf[nfp][0], bf[nfp][2]);
                    mma_f16(acc[mf][2 * nfp + 1], a[mf], bf[nfp][1], bf[nfp][3]);
                }
        }

        if (kt + STAGES - 1 < NKT) load_stage(kt + STAGES - 1);
        else                       cp_commit();

        #pragma unroll
        for (int ks = 1; ks < 4; ks++) {
            uint32_t a[4][4], bf[4][4];
            #pragma unroll
            for (int mf = 0; mf < 4; mf++)
                ldmatrix_x4(a[mf], aBase + (uint32_t)(mf * 2048)
                                 + ((((uint32_t)(2 * ks) + gsel) ^ swA) << 4));
            #pragma unroll
            for (int nfp = 0; nfp < 4; nfp++)
                ldmatrix_x4(bf[nfp], bBase + (uint32_t)(nfp * 2048)
                                   + ((((uint32_t)(2 * ks) + gsel) ^ swB) << 4));
            #pragma unroll
            for (int mf = 0; mf < 4; mf++)
                #pragma unroll
                for (int nfp = 0; nfp < 4; nfp++) {
                    mma_f16(acc[mf][2 * nfp + 0], a[mf], bf[nfp][0], bf[nfp][2]);
                    mma_f16(acc[mf][2 * nfp + 1], a[mf], bf[nfp][1], bf[nfp][3]);
                }
        }
    }

    const int lr = lane >> 2;
    const int lc = lane & 3;
    float* Cg = out + ((size_t)b * SEQ + (size_t)mt * BM) * DOUT + (size_t)nt * BN;
    const float* bias = base_b + (size_t)nt * BN;

    #pragma unroll
    for (int mf = 0; mf < 4; mf++) {
        int row = wm * 64 + mf * 16 + lr;
        #pragma unroll
        for (int nf = 0; nf < 8; nf++) {
            int col = wn * 64 + nf * 8 + lc * 2;
            float b0 = bias[col], b1 = bias[col + 1];
            float2 r0, r1;
            r0.x = acc[mf][nf][0] + b0;
            r0.y = acc[mf][nf][1] + b1;
            r1.x = acc[mf][nf][2] + b0;
            r1.y = acc[mf][nf][3] + b1;
            *(float2*)(Cg + (size_t)row * DOUT + col)       = r0;
            *(float2*)(Cg + (size_t)(row + 8) * DOUT + col) = r1;
        }
    }
}

// ---------------------------------------------------------------------------
// Launch: serial two-launch structure (measured-best topology).
// ---------------------------------------------------------------------------
extern "C" void kernel_launch(void* const* d_in, const int* in_sizes, int n_in,
                              void* d_out, int out_size) {
    const float* x      = (const float*)d_in[0];
    const float* mem_f  = (const float*)d_in[1];
    const float* mem_m  = (const float*)d_in[2];
    const float* mem_s  = (const float*)d_in[3];
    const float* base_w = (const float*)d_in[4];
    const float* base_b = (const float*)d_in[5];
    const float* pd_w   = (const float*)d_in[6];
    const float* pu_w   = (const float*)d_in[7];
    // d_in[8..11]: gate network weights — mathematically dead
    // (softmax sums to 1, mean over the 3-way axis == 1/3 exactly).
    float* out = (float*)d_out;

    cudaFuncSetAttribute(fused_pre_kernel,
                         cudaFuncAttributeMaxDynamicSharedMemorySize, PREP_SMEM_BYTES);
    fused_pre_kernel<<<CONV_BLOCKS + PREP_BLOCKS, 256, PREP_SMEM_BYTES>>>(
        (const float4*)x, base_w, pd_w, pu_w, mem_f, mem_m, mem_s);

    cudaFuncSetAttribute(gemm_kernel,
                         cudaFuncAttributeMaxDynamicSharedMemorySize, SMEM_BYTES);
    gemm_kernel<<<dim3(DOUT / BN, SEQ / BM, B_BATCH), 128, SMEM_BYTES>>>(
        base_b, out);
}